// round 11
// baseline (speedup 1.0000x reference)
#include <cuda_runtime.h>
#include <math.h>

#define Tn 1024
#define Bn 512
#define CH 64
#define NCH 16
#define Hn 20
#define NB 128
#define OUT_DIFF (Tn * Bn * 3)

__device__ float g_cw[1024];   // cw[d] = me[Tn-d]*dt for d in [1,1023]; cw[0]=0

// ---------------- packed f32x2 helpers ----------------
__device__ __forceinline__ unsigned long long pk2(float lo, float hi) {
    unsigned long long r;
    asm("mov.b64 %0, {%1,%2};" : "=l"(r) : "f"(lo), "f"(hi));
    return r;
}
__device__ __forceinline__ void upk2(float& lo, float& hi, unsigned long long v) {
    asm("mov.b64 {%0,%1}, %2;" : "=f"(lo), "=f"(hi) : "l"(v));
}
__device__ __forceinline__ unsigned long long fma2(unsigned long long a,
                                                   unsigned long long b,
                                                   unsigned long long c) {
    unsigned long long d;
    asm("fma.rn.f32x2 %0, %1, %2, %3;" : "=l"(d) : "l"(a), "l"(b), "l"(c));
    return d;
}

// ============================================================
// k_init: MLP -> g_cw; solution row 0; diff row Tn-1 (zeros).
// ============================================================
__global__ void k_init(const float* __restrict__ t, const float* __restrict__ y,
                       const float* __restrict__ w1, const float* __restrict__ b1,
                       const float* __restrict__ w2, const float* __restrict__ b2,
                       const float* __restrict__ w3, const float* __restrict__ b3,
                       const float* __restrict__ w4, const float* __restrict__ b4,
                       float* __restrict__ out) {
    __shared__ float sw2[Hn * Hn], sw3[Hn * Hn];
    __shared__ float sw1[Hn], sb1[Hn], sb2[Hn], sb3[Hn], sw4[Hn];
    int tid = threadIdx.x;
    for (int i = tid; i < Hn * Hn; i += 256) { sw2[i] = w2[i]; sw3[i] = w3[i]; }
    if (tid < Hn) {
        sw1[tid] = w1[tid]; sb1[tid] = b1[tid];
        sb2[tid] = b2[tid]; sb3[tid] = b3[tid]; sw4[tid] = w4[tid];
    }
    __syncthreads();

    int r = blockIdx.x * 256 + tid;
    float dt = t[0] - t[1];
    float tv = t[r];

    float h1[Hn], h2[Hn];
#pragma unroll
    for (int j = 0; j < Hn; j++) h1[j] = tanhf(tv * sw1[j] + sb1[j]);
#pragma unroll
    for (int j = 0; j < Hn; j++) {
        float a = sb2[j];
#pragma unroll
        for (int i = 0; i < Hn; i++) a += h1[i] * sw2[i * Hn + j];
        h2[j] = tanhf(a);
    }
#pragma unroll
    for (int j = 0; j < Hn; j++) {
        float a = sb3[j];
#pragma unroll
        for (int i = 0; i < Hn; i++) a += h2[i] * sw3[i * Hn + j];
        h1[j] = tanhf(a);
    }
    float a = b4[0];
#pragma unroll
    for (int i = 0; i < Hn; i++) a += h1[i] * sw4[i];
    float me = 1.0f / (1.0f + expf(-a));

    if (r > 0) g_cw[Tn - r] = me * dt;
    else       g_cw[0] = 0.0f;

    if (r < Bn) {
        float S0 = y[r * 3 + 0], I0 = y[r * 3 + 1], R0 = y[r * 3 + 2];
        float* so = out + (size_t)r * 3;
        so[0] = S0; so[1] = I0; so[2] = R0;
        float* df = out + OUT_DIFF + ((size_t)(Tn - 1) * Bn + r) * 3;
        df[0] = 0.0f; df[1] = 0.0f; df[2] = 0.0f;
    }
}

// ============================================================
// B serial steps (identical to R10): 12-cyc recurrence, 4-ahead shfl.
// ============================================================
template <int FIRST>
__device__ __forceinline__ void stepsB(int k, int bb, int bj, int lane,
                                       float& S, float& I, float& Im2, float& Im3, float& Im4,
                                       float& bS, float tot,
                                       float acc0, float acc1,
                                       float dtv, float ngam, float betadt,
                                       float cw1, float cw2, float cw3, float cw4,
                                       const float* __restrict__ cwZ,
                                       float (*Ih)[Tn],
                                       float* __restrict__ out) {
    float svS0 = 0.f, svI0 = 0.f, svdS0 = 0.f, svdI0 = 0.f;
    float svS1, svI1, svdS1, svdI1;
    float preQ[4], preQ2[4];

    const int s0 = FIRST ? 1 : 0;
#pragma unroll
    for (int r = 0; r < 4; r++)
        preQ[(s0 + r) & 3] = __shfl_sync(0xffffffffu, acc0, s0 + r);

    float rest = preQ[s0 & 3];
    rest = fmaf(cw4, Im4, rest);
    rest = fmaf(cw3, Im3, rest);
    rest = fmaf(cw2, Im2, rest);

#pragma unroll
    for (int s = 0; s < 32; s++) {
        if (FIRST && s == 0) continue;
        float integro = fmaf(cw1, I, rest);
        float bSI = bS * I;
        if (s + 4 < 32) preQ[(s + 4) & 3]   = __shfl_sync(0xffffffffu, acc0, s + 4);
        else            preQ2[(s - 28) & 3] = __shfl_sync(0xffffffffu, acc1, s - 28);
        float dI = fmaf(ngam, I, bSI);
        float dS = integro - bSI;
        float Inew = fmaf(dtv, dI, I);
        S  = fmaf(dtv, dS, S);
        bS = fmaf(betadt, dS, bS);
        bool own = (lane == s);
        svS0  = own ? S    : svS0;
        svI0  = own ? Inew : svI0;
        svdS0 = own ? dS   : svdS0;
        svdI0 = own ? dI   : svdI0;
        acc0 = fmaf(cwZ[32 + lane - s], Inew, acc0);
        acc1 = fmaf(cwZ[64 + lane - s], Inew, acc1);
        float pn = (s + 1 < 32) ? preQ[(s + 1) & 3] : preQ2[0];
        rest = pn;
        rest = fmaf(cw4, Im3, rest);
        rest = fmaf(cw3, Im2, rest);
        rest = fmaf(cw2, I, rest);
        Im4 = Im3; Im3 = Im2; Im2 = I; I = Inew;
    }

#pragma unroll
    for (int s2 = 0; s2 < 32; s2++) {
        float integro = fmaf(cw1, I, rest);
        float bSI = bS * I;
        if (s2 + 4 < 32) preQ2[(s2 + 4) & 3] = __shfl_sync(0xffffffffu, acc1, s2 + 4);
        float dI = fmaf(ngam, I, bSI);
        float dS = integro - bSI;
        float Inew = fmaf(dtv, dI, I);
        S  = fmaf(dtv, dS, S);
        bS = fmaf(betadt, dS, bS);
        bool own = (lane == s2);
        svS1  = own ? S    : svS1;
        svI1  = own ? Inew : svI1;
        svdS1 = own ? dS   : svdS1;
        svdI1 = own ? dI   : svdI1;
        acc1 = fmaf(cwZ[32 + lane - s2], Inew, acc1);
        rest = preQ2[(s2 + 1) & 3];
        rest = fmaf(cw4, Im3, rest);
        rest = fmaf(cw3, Im2, rest);
        rest = fmaf(cw2, I, rest);
        Im4 = Im3; Im3 = Im2; Im2 = I; I = Inew;
    }

    float* const diffb = out + OUT_DIFF;
    int j0 = k * CH + lane;
    if (!(FIRST && lane == 0)) {
        float* so = out + ((size_t)j0 * Bn + bb) * 3;
        so[0] = svS0; so[1] = svI0; so[2] = tot - svS0 - svI0;
        float* df = diffb + ((size_t)(j0 - 1) * Bn + bb) * 3;
        df[0] = svdS0; df[1] = svdI0; df[2] = -svdS0 - svdI0;
        Ih[bj][j0] = svI0;
    }
    int j1 = j0 + 32;
    {
        float* so = out + ((size_t)j1 * Bn + bb) * 3;
        so[0] = svS1; so[1] = svI1; so[2] = tot - svS1 - svI1;
        float* df = diffb + ((size_t)(j1 - 1) * Bn + bb) * 3;
        df[0] = svdS1; df[1] = svdI1; df[2] = -svdS1 - svdI1;
        Ih[bj][j1] = svI1;
    }
}

// ============================================================
// mega: 128 blocks x 512 threads. Warps 12-15: B (hi wid priority).
// Warps 0-11: A — 3 warps per batch, 12 m-slices (x4 lane-groups).
// ============================================================
__global__ void __launch_bounds__(512, 1)
mega(const float* __restrict__ t, const float* __restrict__ y,
     const float* __restrict__ beta_p, const float* __restrict__ gamma_p,
     float* __restrict__ out) {
    __shared__ __align__(16) float cwZ[1056];     // 0 for i<=36; else cw[i-32]
    __shared__ __align__(16) float Ih[4][Tn];     // block-local I history
    __shared__ float baseS[2][4][3][CH];          // A partials: [par][batch][slice-warp][s]

    const int tid  = threadIdx.x;
    const int blk  = blockIdx.x;
    const int wid  = tid >> 5;
    const int lane = tid & 31;
    const bool isB = (wid >= 12);
    const int bj   = isB ? (wid - 12) : (wid & 3);   // batch slot
    const int sw   = isB ? 0 : (wid >> 2);           // A slice-warp 0..2
    const int bb   = blk * 4 + bj;

    for (int i = tid; i < 1056; i += 512)
        cwZ[i] = (i <= 36) ? 0.0f : g_cw[i - 32];
    if (tid < 4) Ih[tid][0] = y[(blk * 4 + tid) * 3 + 1];
    __syncthreads();

    const float dtv    = t[0] - t[1];
    const float beta   = beta_p[0];
    const float gamma  = gamma_p[0];
    const float ngam   = -gamma;
    const float betadt = beta * dtv;
    const float cw1 = __ldg(&g_cw[1]), cw2 = __ldg(&g_cw[2]);
    const float cw3 = __ldg(&g_cw[3]), cw4 = __ldg(&g_cw[4]);

    float S = 0.f, I = 0.f, tot = 0.f, bS = 0.f;
    float Im2 = 0.f, Im3 = 0.f, Im4 = 0.f;
    if (isB) {
        S = y[bb * 3 + 0]; I = y[bb * 3 + 1];
        tot = S + I + y[bb * 3 + 2];
        bS  = beta * S;
    }

    for (int k = 0; k < NCH; k++) {
        if (isB) {
            // ---------- seed accumulators ----------
            float acc0, acc1;
            if (k >= 2) {
                acc0 = baseS[k & 1][bj][0][lane]
                     + baseS[k & 1][bj][1][lane]
                     + baseS[k & 1][bj][2][lane];
                acc1 = baseS[k & 1][bj][0][lane + 32]
                     + baseS[k & 1][bj][1][lane + 32]
                     + baseS[k & 1][bj][2][lane + 32];
            } else { acc0 = 0.f; acc1 = 0.f; }
            if (k >= 1) {
                // recent chunk: float4-broadcast Iv, scalar conflict-free coefs
                const float4* Ip4 = (const float4*)&Ih[bj][(k - 1) * CH];
                const float* c0 = &cwZ[96 + lane];
                const float* c1 = &cwZ[128 + lane];
                float a00 = 0.f, a01 = 0.f, a02 = 0.f, a03 = 0.f;
                float a10 = 0.f, a11 = 0.f, a12 = 0.f, a13 = 0.f;
#pragma unroll 4
                for (int q = 0; q < 16; q++) {
                    float4 v = Ip4[q];
                    int m = q * 4;
                    a00 = fmaf(c0[-(m + 0)], v.x, a00);
                    a01 = fmaf(c0[-(m + 1)], v.y, a01);
                    a02 = fmaf(c0[-(m + 2)], v.z, a02);
                    a03 = fmaf(c0[-(m + 3)], v.w, a03);
                    a10 = fmaf(c1[-(m + 0)], v.x, a10);
                    a11 = fmaf(c1[-(m + 1)], v.y, a11);
                    a12 = fmaf(c1[-(m + 2)], v.z, a12);
                    a13 = fmaf(c1[-(m + 3)], v.w, a13);
                }
                acc0 += (a00 + a01) + (a02 + a03);
                acc1 += (a10 + a11) + (a12 + a13);
                stepsB<0>(k, bb, bj, lane, S, I, Im2, Im3, Im4, bS, tot, acc0, acc1,
                          dtv, ngam, betadt, cw1, cw2, cw3, cw4, cwZ, Ih, out);
            } else {
                acc0 = cwZ[32 + lane] * I;
                acc1 = cwZ[64 + lane] * I;
                stepsB<1>(k, bb, bj, lane, S, I, Im2, Im3, Im4, bS, tot, acc0, acc1,
                          dtv, ngam, betadt, cw1, cw2, cw3, cw4, cwZ, Ih, out);
            }
        } else if (k >= 1 && k <= NCH - 2) {
            // ---------- A: history partials for chunk K=k+1, m < 64k ----------
            // 12 slices: slice = sw*4 + lane-group; lane j8 owns 8 consecutive
            // targets; (r, r+4) f32x2 FIFO; float4 Iv + float4 coef refill.
            const int K    = k + 1;
            const int j8   = lane & 7;
            const int g    = lane >> 3;
            const int Q    = 16 * k;               // total quads (M/4)
            const int si   = sw * 4 + g;
            const int q0   = (si * Q) / 12;
            const int q1   = ((si + 1) * Q) / 12;
            const int m0   = 4 * q0;
            const int nq   = q1 - q0;
            const int Cc   = 32 + CH * K + 8 * j8;
            const float* Ihp = Ih[bj];

            unsigned long long P0 = pk2(cwZ[Cc + 0 - m0], cwZ[Cc + 4 - m0]);
            unsigned long long P1 = pk2(cwZ[Cc + 1 - m0], cwZ[Cc + 5 - m0]);
            unsigned long long P2 = pk2(cwZ[Cc + 2 - m0], cwZ[Cc + 6 - m0]);
            unsigned long long P3 = pk2(cwZ[Cc + 3 - m0], cwZ[Cc + 7 - m0]);
            unsigned long long A0 = pk2(0.f, 0.f), A1 = A0, A2 = A0, A3 = A0;

#pragma unroll 2
            for (int qq = 0; qq < nq; qq++) {
                const int m = m0 + 4 * qq;
                float4 Iv4 = *(const float4*)(Ihp + m);            // broadcast
                float4 F   = *(const float4*)(&cwZ[Cc - 4 - m]);   // nc(m..m+3)=F.w,z,y,x
                unsigned long long Iv2;
                float lo, hi;

                Iv2 = pk2(Iv4.x, Iv4.x);
                A0 = fma2(P0, Iv2, A0); A1 = fma2(P1, Iv2, A1);
                A2 = fma2(P2, Iv2, A2); A3 = fma2(P3, Iv2, A3);
                upk2(lo, hi, P3); unsigned long long N0 = pk2(F.w, lo);

                Iv2 = pk2(Iv4.y, Iv4.y);
                A0 = fma2(N0, Iv2, A0); A1 = fma2(P0, Iv2, A1);
                A2 = fma2(P1, Iv2, A2); A3 = fma2(P2, Iv2, A3);
                upk2(lo, hi, P2); unsigned long long N1 = pk2(F.z, lo);

                Iv2 = pk2(Iv4.z, Iv4.z);
                A0 = fma2(N1, Iv2, A0); A1 = fma2(N0, Iv2, A1);
                A2 = fma2(P0, Iv2, A2); A3 = fma2(P1, Iv2, A3);
                upk2(lo, hi, P1); unsigned long long N2 = pk2(F.y, lo);

                Iv2 = pk2(Iv4.w, Iv4.w);
                A0 = fma2(N2, Iv2, A0); A1 = fma2(N1, Iv2, A1);
                A2 = fma2(N0, Iv2, A2); A3 = fma2(P0, Iv2, A3);
                upk2(lo, hi, P0); unsigned long long N3 = pk2(F.x, lo);

                P0 = N3; P1 = N2; P2 = N1; P3 = N0;
            }

            float acc[8];
            upk2(acc[0], acc[4], A0);
            upk2(acc[1], acc[5], A1);
            upk2(acc[2], acc[6], A2);
            upk2(acc[3], acc[7], A3);
#pragma unroll
            for (int r = 0; r < 8; r++) {
                acc[r] += __shfl_xor_sync(0xffffffffu, acc[r], 8);
                acc[r] += __shfl_xor_sync(0xffffffffu, acc[r], 16);
            }
            if (lane < 8) {
                float4* dst = (float4*)&baseS[K & 1][bj][sw][8 * j8];
                dst[0] = make_float4(acc[0], acc[1], acc[2], acc[3]);
                dst[1] = make_float4(acc[4], acc[5], acc[6], acc[7]);
            }
        }
        __syncthreads();
    }
}

// ================= launch: 2 graph nodes =================
extern "C" void kernel_launch(void* const* d_in, const int* in_sizes, int n_in,
                              void* d_out, int out_size) {
    const float* t    = (const float*)d_in[0];
    const float* y    = (const float*)d_in[1];
    const float* w1   = (const float*)d_in[2];
    const float* b1   = (const float*)d_in[3];
    const float* w2   = (const float*)d_in[4];
    const float* b2   = (const float*)d_in[5];
    const float* w3   = (const float*)d_in[6];
    const float* b3   = (const float*)d_in[7];
    const float* w4   = (const float*)d_in[8];
    const float* b4   = (const float*)d_in[9];
    const float* beta = (const float*)d_in[10];
    const float* gamma= (const float*)d_in[11];
    float* out = (float*)d_out;

    k_init<<<4, 256>>>(t, y, w1, b1, w2, b2, w3, b3, w4, b4, out);
    mega<<<NB, 512>>>(t, y, beta, gamma, out);
}

// round 12
// speedup vs baseline: 1.0446x; 1.0446x over previous
#include <cuda_runtime.h>
#include <math.h>

#define Tn 1024
#define Bn 512
#define CH 64
#define NCH 16
#define Hn 20
#define NB 128
#define OUT_DIFF (Tn * Bn * 3)
#define FULLM 0xffffffffu

__device__ float g_cw[1024];   // cw[d] = me[Tn-d]*dt for d in [1,1023]; cw[0]=0

// ---------------- packed f32x2 helpers ----------------
__device__ __forceinline__ unsigned long long pk2(float lo, float hi) {
    unsigned long long r;
    asm("mov.b64 %0, {%1,%2};" : "=l"(r) : "f"(lo), "f"(hi));
    return r;
}
__device__ __forceinline__ void upk2(float& lo, float& hi, unsigned long long v) {
    asm("mov.b64 {%0,%1}, %2;" : "=f"(lo), "=f"(hi) : "l"(v));
}
__device__ __forceinline__ unsigned long long fma2(unsigned long long a,
                                                   unsigned long long b,
                                                   unsigned long long c) {
    unsigned long long d;
    asm("fma.rn.f32x2 %0, %1, %2, %3;" : "=l"(d) : "l"(a), "l"(b), "l"(c));
    return d;
}

// ============================================================
// k_init: MLP -> g_cw; solution row 0; diff row Tn-1 (zeros).
// ============================================================
__global__ void k_init(const float* __restrict__ t, const float* __restrict__ y,
                       const float* __restrict__ w1, const float* __restrict__ b1,
                       const float* __restrict__ w2, const float* __restrict__ b2,
                       const float* __restrict__ w3, const float* __restrict__ b3,
                       const float* __restrict__ w4, const float* __restrict__ b4,
                       float* __restrict__ out) {
    __shared__ float sw2[Hn * Hn], sw3[Hn * Hn];
    __shared__ float sw1[Hn], sb1[Hn], sb2[Hn], sb3[Hn], sw4[Hn];
    int tid = threadIdx.x;
    for (int i = tid; i < Hn * Hn; i += 256) { sw2[i] = w2[i]; sw3[i] = w3[i]; }
    if (tid < Hn) {
        sw1[tid] = w1[tid]; sb1[tid] = b1[tid];
        sb2[tid] = b2[tid]; sb3[tid] = b3[tid]; sw4[tid] = w4[tid];
    }
    __syncthreads();

    int r = blockIdx.x * 256 + tid;
    float dt = t[0] - t[1];
    float tv = t[r];

    float h1[Hn], h2[Hn];
#pragma unroll
    for (int j = 0; j < Hn; j++) h1[j] = tanhf(tv * sw1[j] + sb1[j]);
#pragma unroll
    for (int j = 0; j < Hn; j++) {
        float a = sb2[j];
#pragma unroll
        for (int i = 0; i < Hn; i++) a += h1[i] * sw2[i * Hn + j];
        h2[j] = tanhf(a);
    }
#pragma unroll
    for (int j = 0; j < Hn; j++) {
        float a = sb3[j];
#pragma unroll
        for (int i = 0; i < Hn; i++) a += h2[i] * sw3[i * Hn + j];
        h1[j] = tanhf(a);
    }
    float a = b4[0];
#pragma unroll
    for (int i = 0; i < Hn; i++) a += h1[i] * sw4[i];
    float me = 1.0f / (1.0f + expf(-a));

    if (r > 0) g_cw[Tn - r] = me * dt;
    else       g_cw[0] = 0.0f;

    if (r < Bn) {
        float S0 = y[r * 3 + 0], I0 = y[r * 3 + 1], R0 = y[r * 3 + 2];
        float* so = out + (size_t)r * 3;
        so[0] = S0; so[1] = I0; so[2] = R0;
        float* df = out + OUT_DIFF + ((size_t)(Tn - 1) * Bn + r) * 3;
        df[0] = 0.0f; df[1] = 0.0f; df[2] = 0.0f;
    }
}

// ============================================================
// B serial steps: bS-only recurrence, 3 SELs, window-3, 3-ahead shfl.
// State carried across chunks: bS, I(=I_last), Im2, Im3, tot.
// ============================================================
template <int FIRST>
__device__ __forceinline__ void stepsB(int k, int bb, int bj, int lane,
                                       float& bS, float& I, float& Im2, float& Im3,
                                       float tot,
                                       float acc0, float acc1,
                                       float dtv, float ngam, float betadt,
                                       float inv_beta,
                                       float cw1, float cw2, float cw3,
                                       const float* __restrict__ cwZ,
                                       float (*Ih)[Tn],
                                       float* __restrict__ out) {
    const float bS_in = bS, I_in = I;

    float sv_bS0 = 0.f, sv_I0 = 0.f, sv_G0 = 0.f;
    float sv_bS1, sv_I1, sv_G1;
    float preQ[4], preQ2[4];

    const int s0 = FIRST ? 1 : 0;
#pragma unroll
    for (int r = 0; r < 3; r++)
        preQ[(s0 + r) & 3] = __shfl_sync(FULLM, acc0, s0 + r);

    if (FIRST) { sv_bS0 = bS; sv_I0 = I; }   // lane 0 = entry state (for lane1's pred)

    // rest for first step: extracted + cw2*I[-2] + cw3*I[-3]
    float rest = preQ[s0 & 3];
    rest = fmaf(cw3, Im3, rest);
    rest = fmaf(cw2, Im2, rest);

    // ---------- half 1: steps s0..31 ----------
#pragma unroll
    for (int s = 0; s < 32; s++) {
        if (FIRST && s == 0) continue;
        float integro = fmaf(cw1, I, rest);
        float bSI = bS * I;
        if (s + 3 < 32)      preQ[(s + 3) & 3]  = __shfl_sync(FULLM, acc0, s + 3);
        else if (s >= 29)    preQ2[(s - 29) & 3] = __shfl_sync(FULLM, acc1, s - 29);
        float dI = fmaf(ngam, I, bSI);
        float dS = integro - bSI;
        float Inew = fmaf(dtv, dI, I);
        bS = fmaf(betadt, dS, bS);
        bool own = (lane == s);
        sv_bS0 = own ? bS      : sv_bS0;
        sv_I0  = own ? Inew    : sv_I0;
        sv_G0  = own ? integro : sv_G0;
        acc0 = fmaf(cwZ[32 + lane - s], Inew, acc0);   // d<=3 zeroed
        acc1 = fmaf(cwZ[64 + lane - s], Inew, acc1);
        float pn = (s + 1 < 32) ? preQ[(s + 1) & 3] : preQ2[0];
        rest = fmaf(cw2, I, pn);        // d=2 for target s+1 -> I_{s-1}=I
        rest = fmaf(cw3, Im2, rest);    // d=3 -> I_{s-2}=Im2
        Im3 = Im2; Im2 = I; I = Inew;
    }

    // ---------- half 2: steps 32..63 ----------
#pragma unroll
    for (int s2 = 0; s2 < 32; s2++) {
        float integro = fmaf(cw1, I, rest);
        float bSI = bS * I;
        if (s2 + 3 < 32) preQ2[(s2 + 3) & 3] = __shfl_sync(FULLM, acc1, s2 + 3);
        float dI = fmaf(ngam, I, bSI);
        float dS = integro - bSI;
        float Inew = fmaf(dtv, dI, I);
        bS = fmaf(betadt, dS, bS);
        bool own = (lane == s2);
        sv_bS1 = own ? bS      : sv_bS1;
        sv_I1  = own ? Inew    : sv_I1;
        sv_G1  = own ? integro : sv_G1;
        acc1 = fmaf(cwZ[32 + lane - s2], Inew, acc1);
        float pn = preQ2[(s2 + 1) & 3];            // stale at s2=31: unused next chunk
        rest = fmaf(cw2, I, pn);
        rest = fmaf(cw3, Im2, rest);
        Im3 = Im2; Im2 = I; I = Inew;
    }

    // ---------- flush (off the serial path) ----------
    float* const diffb = out + OUT_DIFF;

    // half1 reconstruction
    {
        float Sv  = sv_bS0 * inv_beta;
        float bSp = __shfl_up_sync(FULLM, sv_bS0, 1);
        float Ip  = __shfl_up_sync(FULLM, sv_I0, 1);
        if (lane == 0) { bSp = bS_in; Ip = I_in; }
        float bSIp = bSp * Ip;
        float dS = sv_G0 - bSIp;                      // bit-exact recompute
        float dI = fmaf(ngam, Ip, bSIp);
        int j0 = k * CH + lane;
        if (!(FIRST && lane == 0)) {
            float* so = out + ((size_t)j0 * Bn + bb) * 3;
            so[0] = Sv; so[1] = sv_I0; so[2] = tot - Sv - sv_I0;
            float* df = diffb + ((size_t)(j0 - 1) * Bn + bb) * 3;
            df[0] = dS; df[1] = dI; df[2] = -dS - dI;
            Ih[bj][j0] = sv_I0;
        }
    }
    // half2 reconstruction
    {
        float Sv   = sv_bS1 * inv_beta;
        float bS31 = __shfl_sync(FULLM, sv_bS0, 31);
        float I31  = __shfl_sync(FULLM, sv_I0, 31);
        float bSp  = __shfl_up_sync(FULLM, sv_bS1, 1);
        float Ip   = __shfl_up_sync(FULLM, sv_I1, 1);
        if (lane == 0) { bSp = bS31; Ip = I31; }
        float bSIp = bSp * Ip;
        float dS = sv_G1 - bSIp;
        float dI = fmaf(ngam, Ip, bSIp);
        int j1 = k * CH + 32 + lane;
        float* so = out + ((size_t)j1 * Bn + bb) * 3;
        so[0] = Sv; so[1] = sv_I1; so[2] = tot - Sv - sv_I1;
        float* df = diffb + ((size_t)(j1 - 1) * Bn + bb) * 3;
        df[0] = dS; df[1] = dI; df[2] = -dS - dI;
        Ih[bj][j1] = sv_I1;
    }
}

// ============================================================
// mega: 128 blocks x 256 threads. Warps 4-7: B (hi priority), 0-3: A.
// ============================================================
__global__ void __launch_bounds__(256, 1)
mega(const float* __restrict__ t, const float* __restrict__ y,
     const float* __restrict__ beta_p, const float* __restrict__ gamma_p,
     float* __restrict__ out) {
    __shared__ __align__(16) float cwZ[1056];     // 0 for i<=35; else cw[i-32]
    __shared__ __align__(16) float Ih[4][Tn];     // block-local I history
    __shared__ float baseS[2][4][CH];             // A partials, parity double-buffered
    __shared__ __align__(16) float REV[4][176];   // reversed coef copies (seed loop)
                                                  // REV[q][j] = cwZ_val(172+q-j)

    const int tid  = threadIdx.x;
    const int blk  = blockIdx.x;
    const int wid  = tid >> 5;
    const int lane = tid & 31;
    const bool isB = (wid >= 4);
    const int bj   = isB ? (wid - 4) : wid;
    const int bb   = blk * 4 + bj;

    for (int i = tid; i < 1056; i += 256)
        cwZ[i] = (i <= 35) ? 0.0f : g_cw[i - 32];
    for (int e = tid; e < 4 * 176; e += 256) {
        int q = e / 176, j = e - q * 176;
        int idx = 172 + q - j;               // cwZ index
        float v = 0.0f;
        if (idx > 35 && idx < 1056) v = g_cw[idx - 32];
        REV[q][j] = v;
    }
    if (tid < 4) Ih[tid][0] = y[(blk * 4 + tid) * 3 + 1];
    __syncthreads();

    const float dtv      = t[0] - t[1];
    const float beta     = beta_p[0];
    const float gamma    = gamma_p[0];
    const float ngam     = -gamma;
    const float betadt   = beta * dtv;
    const float inv_beta = 1.0f / beta;
    const float cw1 = __ldg(&g_cw[1]), cw2 = __ldg(&g_cw[2]), cw3 = __ldg(&g_cw[3]);

    // persistent B state
    float bS = 0.f, I = 0.f, tot = 0.f, Im2 = 0.f, Im3 = 0.f;
    if (isB) {
        float S0 = y[bb * 3 + 0];
        I = y[bb * 3 + 1];
        tot = S0 + I + y[bb * 3 + 2];
        bS  = beta * S0;
    }
    // seed-loop reversed-array bases (valid for B warps)
    const int qr  = (96 + lane) & 3;
    const int j00 = 172 + qr - (96 + lane);  // c0 quad base; c1 = j00 - 32

    for (int k = 0; k < NCH; k++) {
        if (isB) {
            float acc0, acc1;
            if (k >= 2) { acc0 = baseS[k & 1][bj][lane]; acc1 = baseS[k & 1][bj][lane + 32]; }
            else        { acc0 = 0.f; acc1 = 0.f; }
            if (k >= 1) {
                // recent chunk: float4 Iv + float4 reversed-coef loads
                const float4* Ip4 = (const float4*)&Ih[bj][(k - 1) * CH];
                const float* Rq = REV[qr];
                float a00 = 0.f, a01 = 0.f, a02 = 0.f, a03 = 0.f;
                float a10 = 0.f, a11 = 0.f, a12 = 0.f, a13 = 0.f;
#pragma unroll 4
                for (int q = 0; q < 16; q++) {
                    float4 v  = Ip4[q];
                    int m = q * 4;
                    float4 F0 = *(const float4*)(Rq + j00 + m);        // c0: d=64+lane-m
                    float4 F1 = *(const float4*)(Rq + j00 - 32 + m);   // c1: d=96+lane-m
                    a00 = fmaf(F0.x, v.x, a00);
                    a01 = fmaf(F0.y, v.y, a01);
                    a02 = fmaf(F0.z, v.z, a02);
                    a03 = fmaf(F0.w, v.w, a03);
                    a10 = fmaf(F1.x, v.x, a10);
                    a11 = fmaf(F1.y, v.y, a11);
                    a12 = fmaf(F1.z, v.z, a12);
                    a13 = fmaf(F1.w, v.w, a13);
                }
                acc0 += (a00 + a01) + (a02 + a03);
                acc1 += (a10 + a11) + (a12 + a13);
                stepsB<0>(k, bb, bj, lane, bS, I, Im2, Im3, tot, acc0, acc1,
                          dtv, ngam, betadt, inv_beta, cw1, cw2, cw3, cwZ, Ih, out);
            } else {
                acc0 = cwZ[32 + lane] * I;             // I_0 scatter (d<=3 zeroed)
                acc1 = cwZ[64 + lane] * I;
                stepsB<1>(k, bb, bj, lane, bS, I, Im2, Im3, tot, acc0, acc1,
                          dtv, ngam, betadt, inv_beta, cw1, cw2, cw3, cwZ, Ih, out);
            }
        } else if (k >= 1 && k <= NCH - 2) {
            // ---------- A: history partials for chunk K=k+1, m < 64k (R10 form) ----------
            const int K    = k + 1;
            const int j8   = lane & 7;
            const int g    = lane >> 3;
            const int M    = CH * k;
            const int mlen = M >> 2;
            const int m0   = g * mlen;
            const int Cc   = 32 + CH * K + 8 * j8;
            const float* Ihp = Ih[bj];

            unsigned long long P0 = pk2(cwZ[Cc + 0 - m0], cwZ[Cc + 4 - m0]);
            unsigned long long P1 = pk2(cwZ[Cc + 1 - m0], cwZ[Cc + 5 - m0]);
            unsigned long long P2 = pk2(cwZ[Cc + 2 - m0], cwZ[Cc + 6 - m0]);
            unsigned long long P3 = pk2(cwZ[Cc + 3 - m0], cwZ[Cc + 7 - m0]);
            unsigned long long A0 = pk2(0.f, 0.f), A1 = A0, A2 = A0, A3 = A0;

#pragma unroll 2
            for (int m = m0; m < m0 + mlen; m += 4) {
                float4 Iv4 = *(const float4*)(Ihp + m);
                float4 F   = *(const float4*)(&cwZ[Cc - 4 - m]);
                unsigned long long Iv2;
                float lo, hi;

                Iv2 = pk2(Iv4.x, Iv4.x);
                A0 = fma2(P0, Iv2, A0); A1 = fma2(P1, Iv2, A1);
                A2 = fma2(P2, Iv2, A2); A3 = fma2(P3, Iv2, A3);
                upk2(lo, hi, P3); unsigned long long N0 = pk2(F.w, lo);

                Iv2 = pk2(Iv4.y, Iv4.y);
                A0 = fma2(N0, Iv2, A0); A1 = fma2(P0, Iv2, A1);
                A2 = fma2(P1, Iv2, A2); A3 = fma2(P2, Iv2, A3);
                upk2(lo, hi, P2); unsigned long long N1 = pk2(F.z, lo);

                Iv2 = pk2(Iv4.z, Iv4.z);
                A0 = fma2(N1, Iv2, A0); A1 = fma2(N0, Iv2, A1);
                A2 = fma2(P0, Iv2, A2); A3 = fma2(P1, Iv2, A3);
                upk2(lo, hi, P1); unsigned long long N2 = pk2(F.y, lo);

                Iv2 = pk2(Iv4.w, Iv4.w);
                A0 = fma2(N2, Iv2, A0); A1 = fma2(N1, Iv2, A1);
                A2 = fma2(N0, Iv2, A2); A3 = fma2(P0, Iv2, A3);
                upk2(lo, hi, P0); unsigned long long N3 = pk2(F.x, lo);

                P0 = N3; P1 = N2; P2 = N1; P3 = N0;
            }

            float acc[8];
            upk2(acc[0], acc[4], A0);
            upk2(acc[1], acc[5], A1);
            upk2(acc[2], acc[6], A2);
            upk2(acc[3], acc[7], A3);
#pragma unroll
            for (int r = 0; r < 8; r++) {
                acc[r] += __shfl_xor_sync(FULLM, acc[r], 8);
                acc[r] += __shfl_xor_sync(FULLM, acc[r], 16);
            }
            if (lane < 8) {
                float4* dst = (float4*)&baseS[K & 1][bj][8 * j8];
                dst[0] = make_float4(acc[0], acc[1], acc[2], acc[3]);
                dst[1] = make_float4(acc[4], acc[5], acc[6], acc[7]);
            }
        }
        __syncthreads();
    }
}

// ================= launch: 2 graph nodes =================
extern "C" void kernel_launch(void* const* d_in, const int* in_sizes, int n_in,
                              void* d_out, int out_size) {
    const float* t    = (const float*)d_in[0];
    const float* y    = (const float*)d_in[1];
    const float* w1   = (const float*)d_in[2];
    const float* b1   = (const float*)d_in[3];
    const float* w2   = (const float*)d_in[4];
    const float* b2   = (const float*)d_in[5];
    const float* w3   = (const float*)d_in[6];
    const float* b3   = (const float*)d_in[7];
    const float* w4   = (const float*)d_in[8];
    const float* b4   = (const float*)d_in[9];
    const float* beta = (const float*)d_in[10];
    const float* gamma= (const float*)d_in[11];
    float* out = (float*)d_out;

    k_init<<<4, 256>>>(t, y, w1, b1, w2, b2, w3, b3, w4, b4, out);
    mega<<<NB, 256>>>(t, y, beta, gamma, out);
}